// round 1
// baseline (speedup 1.0000x reference)
#include <cuda_runtime.h>

#define NROWS 16384
#define DCOLS 2048

// Scratch for per-row cosine (device global — no allocations allowed).
__device__ float g_row_cos[NROWS];

// One block (256 threads) per row. Each thread: 2 float4 loads per tensor.
__global__ void __launch_bounds__(256) row_cos_kernel(
    const float* __restrict__ cxr, const float* __restrict__ ehr)
{
    const int row = blockIdx.x;
    const float4* __restrict__ a = reinterpret_cast<const float4*>(ehr + (size_t)row * DCOLS);
    const float4* __restrict__ b = reinterpret_cast<const float4*>(cxr + (size_t)row * DCOLS);
    const int t = threadIdx.x;

    float dot = 0.f, na = 0.f, nb = 0.f;

    // 2048 floats = 512 float4 per tensor; 256 threads -> 2 float4 each.
    // Batch all 4 loads up front for MLP.
    float4 a0 = a[t];
    float4 b0 = b[t];
    float4 a1 = a[t + 256];
    float4 b1 = b[t + 256];

    dot += a0.x*b0.x + a0.y*b0.y + a0.z*b0.z + a0.w*b0.w;
    na  += a0.x*a0.x + a0.y*a0.y + a0.z*a0.z + a0.w*a0.w;
    nb  += b0.x*b0.x + b0.y*b0.y + b0.z*b0.z + b0.w*b0.w;

    dot += a1.x*b1.x + a1.y*b1.y + a1.z*b1.z + a1.w*b1.w;
    na  += a1.x*a1.x + a1.y*a1.y + a1.z*a1.z + a1.w*a1.w;
    nb  += b1.x*b1.x + b1.y*b1.y + b1.z*b1.z + b1.w*b1.w;

    // Warp reduction
    #pragma unroll
    for (int o = 16; o > 0; o >>= 1) {
        dot += __shfl_xor_sync(0xffffffffu, dot, o);
        na  += __shfl_xor_sync(0xffffffffu, na,  o);
        nb  += __shfl_xor_sync(0xffffffffu, nb,  o);
    }

    __shared__ float sdot[8], sna[8], snb[8];
    const int w = t >> 5, l = t & 31;
    if (l == 0) { sdot[w] = dot; sna[w] = na; snb[w] = nb; }
    __syncthreads();

    if (t == 0) {
        float d = 0.f, x = 0.f, y = 0.f;
        #pragma unroll
        for (int i = 0; i < 8; i++) { d += sdot[i]; x += sna[i]; y += snb[i]; }
        g_row_cos[row] = d * rsqrtf(x * y);
    }
}

// Single-block deterministic final reduce: out = 1 - mean(cos).
__global__ void __launch_bounds__(1024) final_reduce_kernel(float* __restrict__ out)
{
    const int t = threadIdx.x;
    float s = 0.f;
    #pragma unroll
    for (int i = 0; i < NROWS / 1024; i++)
        s += g_row_cos[t + i * 1024];

    #pragma unroll
    for (int o = 16; o > 0; o >>= 1)
        s += __shfl_xor_sync(0xffffffffu, s, o);

    __shared__ float sw[32];
    const int w = t >> 5, l = t & 31;
    if (l == 0) sw[w] = s;
    __syncthreads();

    if (t == 0) {
        float tot = 0.f;
        #pragma unroll
        for (int i = 0; i < 32; i++) tot += sw[i];
        out[0] = 1.0f - tot / (float)NROWS;
    }
}

extern "C" void kernel_launch(void* const* d_in, const int* in_sizes, int n_in,
                              void* d_out, int out_size)
{
    const float* cxr = (const float*)d_in[0];
    const float* ehr = (const float*)d_in[1];
    float* out = (float*)d_out;

    row_cos_kernel<<<NROWS, 256>>>(cxr, ehr);
    final_reduce_kernel<<<1, 1024>>>(out);
}